// round 2
// baseline (speedup 1.0000x reference)
#include <cuda_runtime.h>
#include <cuda_bf16.h>

// Problem constants (fixed by the dataset)
#define BB 16
#define TT 512
#define DD 384
#define D4 (DD / 4)        // 96 float4 per row
#define MAXLEN 4096

// Scratch (device globals -- no allocation allowed)
__device__ int g_idx[BB * MAXLEN];   // frame -> token index, -1 = invalid (zero-fill)
__device__ int g_mel[BB];            // mel_len per batch (sum of durations, unclamped)

// ---------------------------------------------------------------------------
// Kernel 1: per-batch inclusive scan over durations + scatter frame->token map
// One block per batch, T threads. durations are int32 (JAX x64 disabled).
// ---------------------------------------------------------------------------
__global__ void lr_scan_scatter(const int* __restrict__ dur) {
    __shared__ int s[TT];
    const int b = blockIdx.x;
    const int t = threadIdx.x;

    const int v = dur[b * TT + t];
    s[t] = v;
    __syncthreads();

    // Hillis-Steele inclusive scan (log2(512)=9 steps)
    #pragma unroll
    for (int off = 1; off < TT; off <<= 1) {
        int add = (t >= off) ? s[t - off] : 0;
        __syncthreads();
        s[t] += add;
        __syncthreads();
    }

    const int end   = s[t];
    const int start = end - v;
    const int mel   = s[TT - 1];
    if (t == 0) g_mel[b] = mel;

    const int lim = mel < MAXLEN ? mel : MAXLEN;

    // Token t owns frames [start, end) -- durations are < 8, short loop
    int* gi = g_idx + b * MAXLEN;
    for (int f = start; f < end; ++f) {
        if (f < lim) gi[f] = t;
    }
    // Invalid frames [lim, MAXLEN): mark -1 (output zero there)
    for (int f = lim + t; f < MAXLEN; f += TT) {
        gi[f] = -1;
    }
}

// ---------------------------------------------------------------------------
// Kernel 2: gather. One float4 store per thread. HBM-store-bound.
//   gid -> (bf, d4);  bf -> (b, f)
// idx load is a broadcast 4B load shared by 96 threads of the same frame
// (L1-cached). Output uses streaming stores so the 100MB write stream does
// not evict the 12.6MB x working set from L2.
// ---------------------------------------------------------------------------
__global__ void __launch_bounds__(256) lr_gather(const float4* __restrict__ x,
                                                 float4* __restrict__ out) {
    const unsigned gid = blockIdx.x * 256u + threadIdx.x;   // < 6,291,456
    const unsigned d4  = gid % D4;
    const unsigned bf  = gid / D4;          // b * MAXLEN + f
    const unsigned b   = bf / MAXLEN;

    const int idx = __ldg(&g_idx[bf]);

    float4 val = make_float4(0.f, 0.f, 0.f, 0.f);
    if (idx >= 0) {
        val = __ldg(&x[(b * TT + (unsigned)idx) * D4 + d4]);
    }
    __stcs(&out[gid], val);
}

// ---------------------------------------------------------------------------
// Kernel 3: write mel_len into the tail of the output buffer.
// mode 1: as float32 (B extra f32 slots)
// mode 2: as int64   (2*B extra f32 slots, reinterpreted)
// mode 3: as int32 bit-pattern (B extra i32 slots) -- not selectable by size
//         alone vs mode 1; default to float since __output__ dtype is f32.
// ---------------------------------------------------------------------------
__global__ void lr_tail(float* __restrict__ out, int mode) {
    const int b = threadIdx.x;
    if (b >= BB) return;
    const long long base = (long long)BB * MAXLEN * DD;
    if (mode == 1) {
        out[base + b] = (float)g_mel[b];
    } else if (mode == 2) {
        long long* o = (long long*)(out + base);
        o[b] = (long long)g_mel[b];
    }
}

extern "C" void kernel_launch(void* const* d_in, const int* in_sizes, int n_in,
                              void* d_out, int out_size) {
    const float* x   = (const float*)d_in[0];
    const int*   dur = (const int*)d_in[1];   // int32: JAX x64 disabled
    // d_in[2] = max_len scalar (compile-time constant 4096 for this problem)

    lr_scan_scatter<<<BB, TT>>>(dur);

    const long long total4 = (long long)BB * MAXLEN * D4;   // 6,291,456 float4
    const int nblk = (int)((total4 + 255) / 256);
    lr_gather<<<nblk, 256>>>((const float4*)x, (float4*)d_out);

    const long long base = (long long)BB * MAXLEN * DD;     // 25,165,824 f32
    int mode = 0;
    if ((long long)out_size == base + BB)        mode = 1;  // mel_len as f32
    else if ((long long)out_size == base + 2*BB) mode = 2;  // mel_len as i64
    if (mode) lr_tail<<<1, 32>>>((float*)d_out, mode);
}